// round 4
// baseline (speedup 1.0000x reference)
#include <cuda_runtime.h>

#define S      112
#define SP     113            // padded pitch for strided smem reads
#define PLANE  (S * S)        // 12544
#define P4     (PLANE / 4)    // 3136 float4 per plane
#define NB     64
#define NC     64

// Fill region: channels [2,64) of every batch, in float4 units.
#define SLAB4   (62 * P4)          // 194432 float4 per batch
#define TOTAL4  (NB * SLAB4)       // 12443648
#define HALF4   (TOTAL4 / 2)

#define NFILL   124                // fill blocks per kernel
#define NCOMP   320                // 256 (c=0 strips) + 64 (c=1)
#define THREADS 256

// Mask facts (xs[i] = i XOR 2, s = xs[i]+xs[j], mul = 14):
//  c==0 keeps s < 196; c==1 keeps s >= 196 (possible only for i,j in [84,111]);
//  c>=2 keeps nothing -> constant 1e-8.

// Scratch for T = W @ X.  Plane p: c==0 -> p=b (full 112 rows valid),
// c==1 -> p=64+b (only rows 84..111 valid).
__device__ float g_T[128 * PLANE];

__device__ __forceinline__ void do_fill(float4* __restrict__ out4,
                                        int start, int end, int fid) {
    const float v = 1e-8f;
    const float4 f = make_float4(v, v, v, v);
    const int stride = NFILL * THREADS;
    for (int idx = start + fid * THREADS + (int)threadIdx.x; idx < end; idx += stride) {
        const int b   = idx / SLAB4;           // const div -> mul/shift
        const int off = idx - b * SLAB4;
        out4[(size_t)b * (NC * P4) + 2 * P4 + off] = f;
    }
}

// ---------------------------------------------------------------------------
// Pass 1: T strips = W[i0:i0+28,:] @ X  (+ first half of the 1e-8 fill)
// smem: sX[112*112] + sWs[28*113]  = 62832 B
// ---------------------------------------------------------------------------
__global__ void k_pass1(const float* __restrict__ x,
                        const float* __restrict__ W,
                        float* __restrict__ out) {
    if (blockIdx.x < NFILL) {
        do_fill((float4*)out, 0, HALF4, blockIdx.x);
        return;
    }
    const int cb  = blockIdx.x - NFILL;
    const int tid = threadIdx.x;

    int b, p, i0;
    if (cb < 256) { b = cb >> 2; p = b;      i0 = (cb & 3) * 28; }
    else          { b = cb - 256; p = 64 + b; i0 = 84; }
    const int c = (cb < 256) ? 0 : 1;

    extern __shared__ float sm[];
    float* sX  = sm;               // [112][112]
    float* sWs = sm + S * S;       // [28][113]

    // Load X plane (float4) and W strip (padded)
    {
        const float4* xs = (const float4*)(x + (size_t)(b * NC + c) * PLANE);
        float4* xd = (float4*)sX;
        for (int i = tid; i < P4; i += THREADS) xd[i] = xs[i];
    }
    for (int i = tid; i < 28 * S; i += THREADS) {
        const int r = i / S, cc = i - r * S;
        sWs[r * SP + cc] = W[(i0 + r) * S + cc];
    }
    __syncthreads();

    if (tid < 224) {
        const int ty = tid / 16, tx = tid - (tid / 16) * 16;  // ty 0..13, tx 0..15
        const int il = ty * 2, j0 = tx * 7;
        float acc[2][7];
        #pragma unroll
        for (int r = 0; r < 2; r++)
            #pragma unroll
            for (int q = 0; q < 7; q++) acc[r][q] = 0.0f;

        #pragma unroll 2
        for (int k = 0; k < S; k++) {
            const float a0 = sWs[il * SP + k];
            const float a1 = sWs[(il + 1) * SP + k];
            float bb[7];
            #pragma unroll
            for (int q = 0; q < 7; q++) bb[q] = sX[k * S + j0 + q];
            #pragma unroll
            for (int q = 0; q < 7; q++) {
                acc[0][q] = fmaf(a0, bb[q], acc[0][q]);
                acc[1][q] = fmaf(a1, bb[q], acc[1][q]);
            }
        }
        float* tb = g_T + (size_t)p * PLANE;
        #pragma unroll
        for (int r = 0; r < 2; r++)
            #pragma unroll
            for (int q = 0; q < 7; q++)
                tb[(i0 + il + r) * S + j0 + q] = acc[r][q];
    }
}

// ---------------------------------------------------------------------------
// Pass 2: Y = T @ W^T, masked select (+ second half of the fill).
// c==0: full plane in 28-row strips. smem sWp[112*113] + sTs[28*113] = 63280 B
// c==1: 28x28 corner + fill rest of channel-1 plane with 1e-8.
// ---------------------------------------------------------------------------
__global__ void k_pass2(const float* __restrict__ W,
                        float* __restrict__ out) {
    if (blockIdx.x < NFILL) {
        do_fill((float4*)out, HALF4, TOTAL4, blockIdx.x);
        return;
    }
    const int cb  = blockIdx.x - NFILL;
    const int tid = threadIdx.x;

    extern __shared__ float sm[];

    if (cb < 256) {
        // ---- c == 0 strip ----
        const int b = cb >> 2, i0 = (cb & 3) * 28;
        float* sWp = sm;               // [112][113]
        float* sTs = sm + S * SP;      // [28][113]

        for (int i = tid; i < S * S; i += THREADS) {
            const int r = i / S, cc = i - r * S;
            sWp[r * SP + cc] = W[i];
        }
        const float* tb = g_T + (size_t)b * PLANE;
        for (int i = tid; i < 28 * S; i += THREADS) {
            const int r = i / S, cc = i - r * S;
            sTs[r * SP + cc] = tb[(i0 + r) * S + cc];
        }
        __syncthreads();

        if (tid < 224) {
            const int ty = tid / 16, tx = tid - (tid / 16) * 16;
            const int il = ty * 2, j0 = tx * 7;
            float acc[2][7];
            #pragma unroll
            for (int r = 0; r < 2; r++)
                #pragma unroll
                for (int q = 0; q < 7; q++) acc[r][q] = 0.0f;

            #pragma unroll 2
            for (int k = 0; k < S; k++) {
                const float a0 = sTs[il * SP + k];
                const float a1 = sTs[(il + 1) * SP + k];
                float bb[7];
                #pragma unroll
                for (int q = 0; q < 7; q++) bb[q] = sWp[(j0 + q) * SP + k];
                #pragma unroll
                for (int q = 0; q < 7; q++) {
                    acc[0][q] = fmaf(a0, bb[q], acc[0][q]);
                    acc[1][q] = fmaf(a1, bb[q], acc[1][q]);
                }
            }
            float* ob = out + (size_t)(b * NC + 0) * PLANE;
            #pragma unroll
            for (int r = 0; r < 2; r++) {
                const int i = i0 + il + r;
                const int si = i ^ 2;
                #pragma unroll
                for (int q = 0; q < 7; q++) {
                    const int j = j0 + q;
                    const int s = si + (j ^ 2);
                    ob[i * S + j] = (s < 196) ? acc[r][q] : 1e-8f;
                }
            }
        }
    } else {
        // ---- c == 1: 28x28 corner + 1e-8 for the rest of the plane ----
        const int b = cb - 256;
        float* sTs = sm;               // [28][113] = T rows 84..111
        float* sWc = sm + 28 * SP;     // [28][113] = W rows 84..111

        const float* tb = g_T + (size_t)(64 + b) * PLANE;
        for (int i = tid; i < 28 * S; i += THREADS) {
            const int r = i / S, cc = i - r * S;
            sTs[r * SP + cc] = tb[(84 + r) * S + cc];
            sWc[r * SP + cc] = W[(84 + r) * S + cc];
        }
        __syncthreads();

        const int ty = tid / 16, tx = tid - (tid / 16) * 16;
        const bool compute = (tid < 224) && (tx < 4);
        float acc[2][7];
        if (compute) {
            const int il = ty * 2, j0 = tx * 7;
            #pragma unroll
            for (int r = 0; r < 2; r++)
                #pragma unroll
                for (int q = 0; q < 7; q++) acc[r][q] = 0.0f;
            #pragma unroll 2
            for (int k = 0; k < S; k++) {
                const float a0 = sTs[il * SP + k];
                const float a1 = sTs[(il + 1) * SP + k];
                float bb[7];
                #pragma unroll
                for (int q = 0; q < 7; q++) bb[q] = sWc[(j0 + q) * SP + k];
                #pragma unroll
                for (int q = 0; q < 7; q++) {
                    acc[0][q] = fmaf(a0, bb[q], acc[0][q]);
                    acc[1][q] = fmaf(a1, bb[q], acc[1][q]);
                }
            }
        }

        float* ob = out + (size_t)(b * NC + 1) * PLANE;
        // Fill channel-1 plane with 1e-8 except the 28x28 corner (disjoint writes).
        {
            const float v = 1e-8f;
            const float4 f = make_float4(v, v, v, v);
            float4* o4 = (float4*)ob;
            for (int i = tid; i < P4; i += THREADS) {
                const int row = i / 28;            // 28 float4 per row
                const int j4  = (i - row * 28) * 4;
                if (row >= 84 && j4 >= 84) continue;  // corner handled below
                o4[i] = f;
            }
        }
        if (compute) {
            const int il = ty * 2, j0c = 84 + tx * 7;
            #pragma unroll
            for (int r = 0; r < 2; r++) {
                const int i = 84 + il + r;
                const int si = i ^ 2;
                #pragma unroll
                for (int q = 0; q < 7; q++) {
                    const int j = j0c + q;
                    const int s = si + (j ^ 2);
                    ob[i * S + j] = (s >= 196) ? acc[r][q] : 1e-8f;
                }
            }
        }
    }
}

// ---------------------------------------------------------------------------
extern "C" void kernel_launch(void* const* d_in, const int* in_sizes, int n_in,
                              void* d_out, int out_size) {
    const float* x = (const float*)d_in[0];   // [64, 64, 112, 112]
    const float* W = (const float*)d_in[1];   // [112, 112]
    float* out = (float*)d_out;

    const int smem1 = (S * S + 28 * SP) * (int)sizeof(float);   // 62832
    const int smem2 = (S * SP + 28 * SP) * (int)sizeof(float);  // 63280
    cudaFuncSetAttribute(k_pass1, cudaFuncAttributeMaxDynamicSharedMemorySize, smem1);
    cudaFuncSetAttribute(k_pass2, cudaFuncAttributeMaxDynamicSharedMemorySize, smem2);

    k_pass1<<<NFILL + NCOMP, THREADS, smem1>>>(x, W, out);
    k_pass2<<<NFILL + NCOMP, THREADS, smem2>>>(W, out);
}

// round 6
// speedup vs baseline: 1.4598x; 1.4598x over previous
#include <cuda_runtime.h>

#define S      112
#define PLANE  (S * S)        // 12544
#define P4     (PLANE / 4)    // 3136
#define NB     64
#define NC     64
#define KH     56             // folded K (DCT even/odd symmetry)
#define WP     57             // pitch for W56 / Te / To
#define TP     113            // pitch for T in sT
#define THREADS 448

// Mask facts (xs[i] = i XOR 2, s = xs[i]+xs[j], mul = 14):
//  c==0 keeps s < 196; c==1 keeps s >= 196 (possible only for i,j in [84,111]);
//  c>=2 keeps nothing -> constant 1e-8.

// smem layout (floats):
//  sW56 : [0, 6384)            W[:,0:56], pitch 57
//  sAe  : [6384, ...)          phase1: Xe (pitch112); phase2: Te (pitch57)
//  sAo  : [12768, ...)         phase1: Xo (pitch112); phase2: To (pitch57)
//  sT   : [19152, 19152+12656) X plane (pitch112), then T (pitch113)
#define SM_W   0
#define SM_A   6384
#define SM_AO  (SM_A + 6384)
#define SM_T   (SM_A + 12768)
#define SM_FLOATS (SM_T + 12656)   // 31808 floats = 127232 bytes

// ---------------------------------------------------------------------------
// Fill channels [2,64) with 1e-8.  grid=(64, NB), no smem -> high occupancy.
// ---------------------------------------------------------------------------
__global__ void fill_kernel(float4* __restrict__ out4) {
    const int b = blockIdx.y;
    const int n = 62 * P4;
    float4* base = out4 + (size_t)b * (NC * P4) + 2 * P4;
    const float v = 1e-8f;
    const float4 f = make_float4(v, v, v, v);
    const int stride = gridDim.x * blockDim.x;
    for (int i = blockIdx.x * blockDim.x + threadIdx.x; i < n; i += stride)
        base[i] = f;
}

// ---------------------------------------------------------------------------
// DCT with even/odd folding. One block per (b,c) plane, c in {0,1}.
// All __syncthreads() are reached unconditionally by all 448 threads.
// ---------------------------------------------------------------------------
__global__ void __launch_bounds__(THREADS, 1)
dct_kernel(const float* __restrict__ x,
           const float* __restrict__ W,
           float* __restrict__ out) {
#if __CUDA_ARCH__ >= 900
    if (threadIdx.x == 0) cudaTriggerProgrammaticLaunchCompletion();
#endif
    extern __shared__ float sm[];
    float* sW56 = sm + SM_W;
    float* sAe  = sm + SM_A;    // Xe / Te
    float* sAo  = sm + SM_AO;   // Xo / To
    float* sT   = sm + SM_T;

    const int bx  = blockIdx.x;            // 0..127
    const int c   = (bx >= 64);
    const int b   = c ? (bx - 64) : bx;
    const int tid = threadIdx.x;
    const int ty  = tid >> 4;              // 0..27
    const int tx  = tid & 15;              // 0..15
    const int i0  = ty * 4;                // output row base
    const int colbase = ((tx >> 1) * 14) + (tx & 1);  // 7 same-parity cols: colbase+2q

    float* ob = out + (size_t)(b * NC + c) * PLANE;

    // c==1: fill the plane early (everything except the 28x28 corner).
    if (c) {
        const float v = 1e-8f;
        const float4 f = make_float4(v, v, v, v);
        float4* o4 = (float4*)ob;
        for (int i = tid; i < P4; i += THREADS) {
            const int row = i / 28;
            const int j4  = (i - row * 28) * 4;
            if (row >= 84 && j4 >= 84) continue;  // corner written by GEMM2
            o4[i] = f;
        }
    }

    // Load W[:,0:56] (pitch 57) and X plane (contiguous into sT).
    for (int idx = tid; idx < S * KH; idx += THREADS) {
        const int r = idx / KH, k = idx - r * KH;
        sW56[r * WP + k] = W[r * S + k];
    }
    {
        const float4* xs = (const float4*)(x + (size_t)(b * NC + c) * PLANE);
        float4* xd = (float4*)sT;
        for (int i = tid; i < P4; i += THREADS) xd[i] = xs[i];
    }
    __syncthreads();

    // Fold 1: Xe/Xo[k][j] = X[k][j] +/- X[111-k][j], k<56 (pitch 112).
    for (int idx = tid; idx < KH * S; idx += THREADS) {
        const int k = idx / S, j = idx - k * S;
        const float x0 = sT[k * S + j];
        const float x1 = sT[(111 - k) * S + j];
        sAe[k * S + j] = x0 + x1;
        sAo[k * S + j] = x0 - x1;
    }
    __syncthreads();   // X fully consumed; sT free for T

    // GEMM1: T[i][j] = sum_{k<56} W[i,k] * (i even ? Xe : Xo)[k][j]
    const bool act1 = (c == 0) || (ty >= 21);   // c==1 needs rows 84..111 only
    if (act1) {
        float acc[4][7];
        #pragma unroll
        for (int r = 0; r < 4; r++)
            #pragma unroll
            for (int q = 0; q < 7; q++) acc[r][q] = 0.0f;

        for (int k = 0; k < KH; k++) {
            const float a0 = sW56[(i0 + 0) * WP + k];
            const float a1 = sW56[(i0 + 1) * WP + k];
            const float a2 = sW56[(i0 + 2) * WP + k];
            const float a3 = sW56[(i0 + 3) * WP + k];
            float be[7], bo[7];
            #pragma unroll
            for (int q = 0; q < 7; q++) {
                be[q] = sAe[k * S + colbase + 2 * q];
                bo[q] = sAo[k * S + colbase + 2 * q];
            }
            #pragma unroll
            for (int q = 0; q < 7; q++) {
                acc[0][q] = fmaf(a0, be[q], acc[0][q]);
                acc[1][q] = fmaf(a1, bo[q], acc[1][q]);
                acc[2][q] = fmaf(a2, be[q], acc[2][q]);
                acc[3][q] = fmaf(a3, bo[q], acc[3][q]);
            }
        }
        #pragma unroll
        for (int r = 0; r < 4; r++)
            #pragma unroll
            for (int q = 0; q < 7; q++)
                sT[(i0 + r) * TP + colbase + 2 * q] = acc[r][q];
    }
    __syncthreads();   // T complete

    // Fold 2: Te/To[i][l] = T[i][l] +/- T[i][111-l], l<56 (pitch 57).
    if (c == 0) {
        for (int idx = tid; idx < S * KH; idx += THREADS) {
            const int i = idx / KH, l = idx - i * KH;
            const float t0 = sT[i * TP + l];
            const float t1 = sT[i * TP + 111 - l];
            sAe[i * WP + l] = t0 + t1;
            sAo[i * WP + l] = t0 - t1;
        }
    } else {
        for (int idx = tid; idx < 28 * KH; idx += THREADS) {
            const int r = idx / KH, l = idx - r * KH;
            const int i = 84 + r;
            const float t0 = sT[i * TP + l];
            const float t1 = sT[i * TP + 111 - l];
            sAe[i * WP + l] = t0 + t1;
            sAo[i * WP + l] = t0 - t1;
        }
    }
    __syncthreads();

    // GEMM2: Y[i][j] = sum_{l<56} W[j,l] * (j even ? Te : To)[i][l], masked write.
    const bool act2 = (c == 0) || (ty >= 21 && tx >= 12);
    if (act2) {
        const float* Tsel = (tx & 1) ? sAo : sAe;
        float acc[4][7];
        #pragma unroll
        for (int r = 0; r < 4; r++)
            #pragma unroll
            for (int q = 0; q < 7; q++) acc[r][q] = 0.0f;

        for (int l = 0; l < KH; l++) {
            float a[4];
            #pragma unroll
            for (int r = 0; r < 4; r++) a[r] = Tsel[(i0 + r) * WP + l];
            float bb[7];
            #pragma unroll
            for (int q = 0; q < 7; q++) bb[q] = sW56[(colbase + 2 * q) * WP + l];
            #pragma unroll
            for (int r = 0; r < 4; r++)
                #pragma unroll
                for (int q = 0; q < 7; q++)
                    acc[r][q] = fmaf(a[r], bb[q], acc[r][q]);
        }

        #pragma unroll
        for (int r = 0; r < 4; r++) {
            const int i  = i0 + r;
            const int si = i ^ 2;
            #pragma unroll
            for (int q = 0; q < 7; q++) {
                const int j = colbase + 2 * q;
                const int s = si + (j ^ 2);
                const bool keep = c ? (s >= 196) : (s < 196);
                ob[i * S + j] = keep ? acc[r][q] : 1e-8f;
            }
        }
    }
}

// ---------------------------------------------------------------------------
extern "C" void kernel_launch(void* const* d_in, const int* in_sizes, int n_in,
                              void* d_out, int out_size) {
    const float* x = (const float*)d_in[0];   // [64, 64, 112, 112]
    const float* W = (const float*)d_in[1];   // [112, 112]
    float* out = (float*)d_out;

    const int smem = SM_FLOATS * (int)sizeof(float);   // 127232
    cudaFuncSetAttribute(dct_kernel, cudaFuncAttributeMaxDynamicSharedMemorySize, smem);

    // 1) compute kernel: 128 blocks land immediately, trigger PDL at entry.
    dct_kernel<<<128, THREADS, smem>>>(x, W, out);

    // 2) bulk 1e-8 fill, allowed to start before dct completes (disjoint output).
    cudaLaunchConfig_t cfg = {};
    cfg.gridDim  = dim3(64, NB);
    cfg.blockDim = dim3(256);
    cfg.dynamicSmemBytes = 0;
    cfg.stream = 0;
    cudaLaunchAttribute attr[1];
    attr[0].id = cudaLaunchAttributeProgrammaticStreamSerialization;
    attr[0].val.programmaticStreamSerializationAllowed = 1;
    cfg.attrs = attr;
    cfg.numAttrs = 1;
    cudaLaunchKernelEx(&cfg, fill_kernel, (float4*)out);
}